// round 14
// baseline (speedup 1.0000x reference)
#include <cuda_runtime.h>
#include <cstdint>

// Problem constants
static constexpr int Bb = 4, T = 2048, D = 512, Hh = 8, HK = 64;
static constexpr int MROWS = Bb * T;          // 8192
static constexpr long QKV_STRIDE = 3 * D;     // 1536

// Scratch (device globals: allocation-free)
__device__ float g_qkv[MROWS * 3 * D];        // [8192, 1536]  (Q | K | V)
__device__ float g_attn[MROWS * D];           // [8192, 512]   (B,T,H*K)

// ---------------------------------------------------------------------------
// Helpers (baseline PTX only — no 'a'-suffix ISA)
// ---------------------------------------------------------------------------
__device__ __forceinline__ uint32_t tf32r(float f) {
    uint32_t u;
    asm("cvt.rna.tf32.f32 %0, %1;" : "=r"(u) : "f"(f));
    return u;
}
__device__ __forceinline__ void mma_tf32(float* c, const uint32_t* a,
                                         uint32_t b0, uint32_t b1) {
    asm volatile(
        "mma.sync.aligned.m16n8k8.row.col.f32.tf32.tf32.f32 "
        "{%0,%1,%2,%3}, {%4,%5,%6,%7}, {%8,%9}, {%0,%1,%2,%3};"
        : "+f"(c[0]), "+f"(c[1]), "+f"(c[2]), "+f"(c[3])
        : "r"(a[0]), "r"(a[1]), "r"(a[2]), "r"(a[3]), "r"(b0), "r"(b1));
}

// ---------------------------------------------------------------------------
// tf32 mma.sync GEMM: C[M,N] = A[M,512] @ B[N,512]^T (+bias).
// 128x128 tile, 256 thr = 8 warps (4 m x 2 n), warp tile 32x64.
// BK=32, double-buffered smem (pad 36), register prefetch.  (unchanged R7)
// ---------------------------------------------------------------------------
template<bool HAS_BIAS>
__global__ void __launch_bounds__(256)
gemm_mma_kernel(const float* __restrict__ A, const float* __restrict__ Bw,
                const float* __restrict__ bias, float* __restrict__ C, int N)
{
    extern __shared__ uint32_t sm[];
    constexpr int PAD = 36;
    uint32_t* const A0 = sm;                // stage area: [2][128][36]
    uint32_t* const B0 = sm + 2 * 128 * PAD;

    const int tid = threadIdx.x, lane = tid & 31, w = tid >> 5;
    const int mw = w & 3, nw = w >> 2;
    const int m0 = blockIdx.y * 128, n0 = blockIdx.x * 128;
    const int r = lane >> 2, cq = lane & 3;

    const int c4 = tid & 7, row_b = tid >> 3;
    const float* Ag = A + (long)(m0 + row_b) * 512 + c4 * 4;
    const float* Bg = Bw + (long)(n0 + row_b) * 512 + c4 * 4;

    float acc[2][8][4] = {};
    float4 ra[4], rb[4];

#pragma unroll
    for (int i = 0; i < 4; i++) {
        ra[i] = *(const float4*)(Ag + (long)(32 * i) * 512);
        rb[i] = *(const float4*)(Bg + (long)(32 * i) * 512);
    }
#pragma unroll
    for (int i = 0; i < 4; i++) {
        uint4 ua = {tf32r(ra[i].x), tf32r(ra[i].y), tf32r(ra[i].z), tf32r(ra[i].w)};
        *(uint4*)&A0[(row_b + 32 * i) * PAD + c4 * 4] = ua;
        uint4 ub = {tf32r(rb[i].x), tf32r(rb[i].y), tf32r(rb[i].z), tf32r(rb[i].w)};
        *(uint4*)&B0[(row_b + 32 * i) * PAD + c4 * 4] = ub;
    }
    __syncthreads();
#pragma unroll
    for (int i = 0; i < 4; i++) {
        ra[i] = *(const float4*)(Ag + (long)(32 * i) * 512 + 32);
        rb[i] = *(const float4*)(Bg + (long)(32 * i) * 512 + 32);
    }

    for (int ch = 0; ch < 16; ch++) {
        const uint32_t* as = A0 + (ch & 1) * 128 * PAD;
        const uint32_t* bs = B0 + (ch & 1) * 128 * PAD;
#pragma unroll
        for (int kt = 0; kt < 4; kt++) {
            const int k0 = kt * 8;
            uint32_t af[2][4];
#pragma unroll
            for (int mt = 0; mt < 2; mt++) {
                const int rr = mw * 32 + mt * 16 + r;
                af[mt][0] = as[rr * PAD + k0 + cq];
                af[mt][1] = as[(rr + 8) * PAD + k0 + cq];
                af[mt][2] = as[rr * PAD + k0 + cq + 4];
                af[mt][3] = as[(rr + 8) * PAD + k0 + cq + 4];
            }
            uint32_t bf[8][2];
#pragma unroll
            for (int t = 0; t < 8; t++) {
                const int nr = nw * 64 + t * 8 + r;
                bf[t][0] = bs[nr * PAD + k0 + cq];
                bf[t][1] = bs[nr * PAD + k0 + cq + 4];
            }
#pragma unroll
            for (int mt = 0; mt < 2; mt++)
#pragma unroll
                for (int t = 0; t < 8; t++)
                    mma_tf32(acc[mt][t], af[mt], bf[t][0], bf[t][1]);
        }
        if (ch < 15) {
            uint32_t* aw = A0 + ((ch + 1) & 1) * 128 * PAD;
            uint32_t* bw = B0 + ((ch + 1) & 1) * 128 * PAD;
#pragma unroll
            for (int i = 0; i < 4; i++) {
                uint4 ua = {tf32r(ra[i].x), tf32r(ra[i].y), tf32r(ra[i].z), tf32r(ra[i].w)};
                *(uint4*)&aw[(row_b + 32 * i) * PAD + c4 * 4] = ua;
                uint4 ub = {tf32r(rb[i].x), tf32r(rb[i].y), tf32r(rb[i].z), tf32r(rb[i].w)};
                *(uint4*)&bw[(row_b + 32 * i) * PAD + c4 * 4] = ub;
            }
            __syncthreads();
            if (ch < 14) {
                const int kn = (ch + 2) * 32;
#pragma unroll
                for (int i = 0; i < 4; i++) {
                    ra[i] = *(const float4*)(Ag + (long)(32 * i) * 512 + kn);
                    rb[i] = *(const float4*)(Bg + (long)(32 * i) * 512 + kn);
                }
            }
        }
    }

#pragma unroll
    for (int mt = 0; mt < 2; mt++) {
        const int row0 = m0 + mw * 32 + mt * 16 + r;
#pragma unroll
        for (int t = 0; t < 8; t++) {
            const int col = n0 + nw * 64 + t * 8 + 2 * cq;
            float2 b2 = {0.f, 0.f};
            if (HAS_BIAS) b2 = *(const float2*)(bias + col);
            float2 v0 = {acc[mt][t][0] + b2.x, acc[mt][t][1] + b2.y};
            *(float2*)(C + (long)row0 * N + col) = v0;
            float2 v1 = {acc[mt][t][2] + b2.x, acc[mt][t][3] + b2.y};
            *(float2*)(C + (long)(row0 + 8) * N + col) = v1;
        }
    }
}

// ---------------------------------------------------------------------------
// Flash attention, tf32 mma.sync. 128-query tile, 256 thr (8 warps x m16).
// Reversed q-tile schedule (heavy CTAs first) + fully-masked-tile warp skip.
// Causal comparisons use GLOBAL rows (q0 + local) vs absolute key columns.
// Smem: Qb[128][68], Kb[64][68], Vb[64][72], Pb[128][68]  (105472 B).
// ---------------------------------------------------------------------------
__global__ void __launch_bounds__(256, 2)
flash_mma_kernel(const float* __restrict__ qkv, float* __restrict__ attn_out)
{
    extern __shared__ uint32_t fsm[];
    uint32_t* const Qb = fsm;                              // [128][68]
    uint32_t* const Kb = fsm + 128 * 68;                   // [64][68]
    uint32_t* const Vb = fsm + 128 * 68 + 64 * 68;         // [64][72]
    uint32_t* const Pb = fsm + 128 * 68 + 64 * 68 + 64 * 72; // [128][68]

    const int tid = threadIdx.x, lane = tid & 31, w = tid >> 5;
    const int r = lane >> 2, cq = lane & 3;
    const int bh = blockIdx.y, b = bh >> 3, h = bh & 7;
    const int qi = gridDim.x - 1 - blockIdx.x;   // reversed: heavy CTAs first
    const int q0 = qi * 128;
    const float* base = qkv + (long)b * T * QKV_STRIDE + h * HK;

    const int c4 = tid & 15, rowq = tid >> 4;    // loader: 16 rows/iter

    // Load Q tile (tf32-rounded); visible after first loop-top sync.
#pragma unroll
    for (int i = 0; i < 8; i++) {
        const int row = rowq + 16 * i;
        float4 v = *(const float4*)(base + (long)(q0 + row) * QKV_STRIDE + c4 * 4);
        uint4 u = {tf32r(v.x), tf32r(v.y), tf32r(v.z), tf32r(v.w)};
        *(uint4*)&Qb[row * 68 + c4 * 4] = u;
    }

    float m0_ = -1e30f, m1_ = -1e30f, l0_ = 0.f, l1_ = 0.f;
    float oacc[8][4] = {};
    const int r0 = w * 16 + r;                   // local rows r0, r0+8
    const int gr0 = q0 + r0;                     // GLOBAL row of this thread
    const int wrow_max = q0 + w * 16 + 15;       // warp's max global row
    const int wrow_min = q0 + w * 16;            // warp's min global row
    const int ntiles = 2 * qi + 2;

    for (int t0 = 0; t0 < ntiles; t0++) {
        const int j0 = t0 * 64;                  // absolute key column base
        __syncthreads();   // prior readers of Kb/Vb done; Qb visible on t0=0
        {
            const float* kb = base + D;
            const float* vb = base + 2 * D;
#pragma unroll
            for (int i = 0; i < 4; i++) {
                const int row = rowq + 16 * i;
                float4 kv = *(const float4*)(kb + (long)(j0 + row) * QKV_STRIDE + c4 * 4);
                uint4 uk = {tf32r(kv.x), tf32r(kv.y), tf32r(kv.z), tf32r(kv.w)};
                *(uint4*)&Kb[row * 68 + c4 * 4] = uk;
                float4 vv = *(const float4*)(vb + (long)(j0 + row) * QKV_STRIDE + c4 * 4);
                uint4 uv = {tf32r(vv.x), tf32r(vv.y), tf32r(vv.z), tf32r(vv.w)};
                *(uint4*)&Vb[row * 72 + c4 * 4] = uv;
            }
        }
        __syncthreads();

        // Warp-level skip: tile entirely above this warp's rows -> all masked.
        if (j0 > wrow_max) continue;

        // S = Q @ K^T  (warp: 16x64)
        float s[8][4] = {};
#pragma unroll
        for (int kt = 0; kt < 8; kt++) {
            const int k0 = kt * 8;
            uint32_t a[4];
            a[0] = Qb[r0 * 68 + k0 + cq];
            a[1] = Qb[(r0 + 8) * 68 + k0 + cq];
            a[2] = Qb[r0 * 68 + k0 + cq + 4];
            a[3] = Qb[(r0 + 8) * 68 + k0 + cq + 4];
#pragma unroll
            for (int t = 0; t < 8; t++) {
                const uint32_t b0 = Kb[(t * 8 + r) * 68 + k0 + cq];
                const uint32_t b1 = Kb[(t * 8 + r) * 68 + k0 + cq + 4];
                mma_tf32(s[t], a, b0, b1);
            }
        }

        // scale + causal mask (only when tile intersects diagonal for warp)
        const bool full = (j0 + 63 <= wrow_min);   // max col <= min global row
#pragma unroll
        for (int t = 0; t < 8; t++) {
            s[t][0] *= 0.125f; s[t][1] *= 0.125f;
            s[t][2] *= 0.125f; s[t][3] *= 0.125f;
            if (!full) {
                const int j = j0 + t * 8 + 2 * cq;   // absolute key column
                if (j     > gr0)     s[t][0] = -1e30f;
                if (j + 1 > gr0)     s[t][1] = -1e30f;
                if (j     > gr0 + 8) s[t][2] = -1e30f;
                if (j + 1 > gr0 + 8) s[t][3] = -1e30f;
            }
        }

        // online softmax (rows r0, r0+8; 4 lanes share a row)
        float rm0 = -1e30f, rm1 = -1e30f;
#pragma unroll
        for (int t = 0; t < 8; t++) {
            rm0 = fmaxf(rm0, fmaxf(s[t][0], s[t][1]));
            rm1 = fmaxf(rm1, fmaxf(s[t][2], s[t][3]));
        }
        rm0 = fmaxf(rm0, __shfl_xor_sync(0xffffffffu, rm0, 1));
        rm0 = fmaxf(rm0, __shfl_xor_sync(0xffffffffu, rm0, 2));
        rm1 = fmaxf(rm1, __shfl_xor_sync(0xffffffffu, rm1, 1));
        rm1 = fmaxf(rm1, __shfl_xor_sync(0xffffffffu, rm1, 2));
        const float nm0 = fmaxf(m0_, rm0), nm1 = fmaxf(m1_, rm1);
        const float al0 = __expf(m0_ - nm0), al1 = __expf(m1_ - nm1);
        m0_ = nm0; m1_ = nm1;

        float rs0 = 0.f, rs1 = 0.f;
#pragma unroll
        for (int t = 0; t < 8; t++) {
            const float p0 = __expf(s[t][0] - nm0);
            const float p1 = __expf(s[t][1] - nm0);
            const float p2 = __expf(s[t][2] - nm1);
            const float p3 = __expf(s[t][3] - nm1);
            rs0 += p0 + p1; rs1 += p2 + p3;
            const int j = t * 8 + 2 * cq;
            Pb[r0 * 68 + j]           = tf32r(p0);
            Pb[r0 * 68 + j + 1]       = tf32r(p1);
            Pb[(r0 + 8) * 68 + j]     = tf32r(p2);
            Pb[(r0 + 8) * 68 + j + 1] = tf32r(p3);
        }
        rs0 += __shfl_xor_sync(0xffffffffu, rs0, 1);
        rs0 += __shfl_xor_sync(0xffffffffu, rs0, 2);
        rs1 += __shfl_xor_sync(0xffffffffu, rs1, 1);
        rs1 += __shfl_xor_sync(0xffffffffu, rs1, 2);
        l0_ = l0_ * al0 + rs0;
        l1_ = l1_ * al1 + rs1;
#pragma unroll
        for (int t = 0; t < 8; t++) {
            oacc[t][0] *= al0; oacc[t][1] *= al0;
            oacc[t][2] *= al1; oacc[t][3] *= al1;
        }
        __syncwarp();   // Pb rows are warp-private: cross-lane visibility only

        // O += P @ V
#pragma unroll
        for (int kt = 0; kt < 8; kt++) {
            const int k0 = kt * 8;
            uint32_t a[4];
            a[0] = Pb[r0 * 68 + k0 + cq];
            a[1] = Pb[(r0 + 8) * 68 + k0 + cq];
            a[2] = Pb[r0 * 68 + k0 + cq + 4];
            a[3] = Pb[(r0 + 8) * 68 + k0 + cq + 4];
#pragma unroll
            for (int t = 0; t < 8; t++) {
                const uint32_t b0 = Vb[(k0 + cq) * 72 + t * 8 + r];
                const uint32_t b1 = Vb[(k0 + cq + 4) * 72 + t * 8 + r];
                mma_tf32(oacc[t], a, b0, b1);
            }
        }
    }

    // Epilogue: normalize + write [B,T,H*K]
    const float inv0 = 1.f / l0_, inv1 = 1.f / l1_;
    float* ob = attn_out + ((long)b * T + q0) * D + h * HK;
#pragma unroll
    for (int t = 0; t < 8; t++) {
        const int col = t * 8 + 2 * cq;
        float2 v0 = {oacc[t][0] * inv0, oacc[t][1] * inv0};
        *(float2*)(ob + (long)r0 * D + col) = v0;
        float2 v1 = {oacc[t][2] * inv1, oacc[t][3] * inv1};
        *(float2*)(ob + (long)(r0 + 8) * D + col) = v1;
    }
}

// ---------------------------------------------------------------------------
extern "C" void kernel_launch(void* const* d_in, const int* in_sizes, int n_in,
                              void* d_out, int out_size)
{
    (void)out_size;
    const float *x = nullptr, *w_qkv = nullptr, *w_proj = nullptr, *b_proj = nullptr;
    for (int i = 0; i < n_in; i++) {
        switch (in_sizes[i]) {
            case MROWS * D: x      = (const float*)d_in[i]; break; // 4194304
            case 3 * D * D: w_qkv  = (const float*)d_in[i]; break; // 786432
            case D * D:     w_proj = (const float*)d_in[i]; break; // 262144
            case D:         b_proj = (const float*)d_in[i]; break; // 512
        }
    }
    float* out = (float*)d_out;

    float* qkv_buf = nullptr;
    float* attn_buf = nullptr;
    cudaGetSymbolAddress((void**)&qkv_buf, g_qkv);
    cudaGetSymbolAddress((void**)&attn_buf, g_attn);

    const int gemm_smem = 4 * 128 * 36 * 4;                          // 73728
    const int attn_smem = (2 * 128 * 68 + 64 * 68 + 64 * 72) * 4;    // 105472
    cudaFuncSetAttribute(gemm_mma_kernel<false>,
                         cudaFuncAttributeMaxDynamicSharedMemorySize, gemm_smem);
    cudaFuncSetAttribute(gemm_mma_kernel<true>,
                         cudaFuncAttributeMaxDynamicSharedMemorySize, gemm_smem);
    cudaFuncSetAttribute(flash_mma_kernel,
                         cudaFuncAttributeMaxDynamicSharedMemorySize, attn_smem);

    // 1) QKV projection: [8192,1536] = x @ w_qkv^T
    {
        dim3 grid(3 * D / 128, MROWS / 128);   // (12, 64)
        gemm_mma_kernel<false><<<grid, 256, gemm_smem>>>(x, w_qkv, nullptr,
                                                         qkv_buf, 3 * D);
    }
    // 2) Causal flash attention (tf32 mma, 128-query tiles)
    {
        dim3 grid(T / 128, Bb * Hh);           // (16, 32)
        flash_mma_kernel<<<grid, 256, attn_smem>>>(qkv_buf, attn_buf);
    }
    // 3) Output projection + bias
    {
        dim3 grid(D / 128, MROWS / 128);       // (4, 64)
        gemm_mma_kernel<true><<<grid, 256, gemm_smem>>>(attn_buf, w_proj, b_proj,
                                                        out, D);
    }
}

// round 16
// speedup vs baseline: 1.0476x; 1.0476x over previous
#include <cuda_runtime.h>
#include <cstdint>

// Problem constants
static constexpr int Bb = 4, T = 2048, D = 512, Hh = 8, HK = 64;
static constexpr int MROWS = Bb * T;          // 8192
static constexpr long QKV_STRIDE = 3 * D;     // 1536

// Scratch (device globals: allocation-free)
__device__ float g_qkv[MROWS * 3 * D];        // [8192, 1536]  (Q | K | V)
__device__ float g_attn[MROWS * D];           // [8192, 512]   (B,T,H*K)

// ---------------------------------------------------------------------------
// Helpers (baseline PTX only — no 'a'-suffix ISA)
// ---------------------------------------------------------------------------
__device__ __forceinline__ uint32_t tf32r(float f) {
    uint32_t u;
    asm("cvt.rna.tf32.f32 %0, %1;" : "=r"(u) : "f"(f));
    return u;
}
__device__ __forceinline__ void mma_tf32(float* c, const uint32_t* a,
                                         uint32_t b0, uint32_t b1) {
    asm volatile(
        "mma.sync.aligned.m16n8k8.row.col.f32.tf32.tf32.f32 "
        "{%0,%1,%2,%3}, {%4,%5,%6,%7}, {%8,%9}, {%0,%1,%2,%3};"
        : "+f"(c[0]), "+f"(c[1]), "+f"(c[2]), "+f"(c[3])
        : "r"(a[0]), "r"(a[1]), "r"(a[2]), "r"(a[3]), "r"(b0), "r"(b1));
}

// ---------------------------------------------------------------------------
// tf32 mma.sync GEMM: C[M,N] = A[M,512] @ B[N,512]^T (+bias).
// 128x128 tile, 256 thr = 8 warps (4 m x 2 n), warp tile 32x64.
// BK=32, double-buffered smem (pad 36), register prefetch.  (unchanged R7)
// ---------------------------------------------------------------------------
template<bool HAS_BIAS>
__global__ void __launch_bounds__(256, 2)
gemm_mma_kernel(const float* __restrict__ A, const float* __restrict__ Bw,
                const float* __restrict__ bias, float* __restrict__ C, int N)
{
    extern __shared__ uint32_t sm[];
    constexpr int PAD = 36;
    uint32_t* const A0 = sm;                // stage area: [2][128][36]
    uint32_t* const B0 = sm + 2 * 128 * PAD;

    const int tid = threadIdx.x, lane = tid & 31, w = tid >> 5;
    const int mw = w & 3, nw = w >> 2;
    const int m0 = blockIdx.y * 128, n0 = blockIdx.x * 128;
    const int r = lane >> 2, cq = lane & 3;

    const int c4 = tid & 7, row_b = tid >> 3;
    const float* Ag = A + (long)(m0 + row_b) * 512 + c4 * 4;
    const float* Bg = Bw + (long)(n0 + row_b) * 512 + c4 * 4;

    float acc[2][8][4] = {};
    float4 ra[4], rb[4];

#pragma unroll
    for (int i = 0; i < 4; i++) {
        ra[i] = *(const float4*)(Ag + (long)(32 * i) * 512);
        rb[i] = *(const float4*)(Bg + (long)(32 * i) * 512);
    }
#pragma unroll
    for (int i = 0; i < 4; i++) {
        uint4 ua = {tf32r(ra[i].x), tf32r(ra[i].y), tf32r(ra[i].z), tf32r(ra[i].w)};
        *(uint4*)&A0[(row_b + 32 * i) * PAD + c4 * 4] = ua;
        uint4 ub = {tf32r(rb[i].x), tf32r(rb[i].y), tf32r(rb[i].z), tf32r(rb[i].w)};
        *(uint4*)&B0[(row_b + 32 * i) * PAD + c4 * 4] = ub;
    }
    __syncthreads();
#pragma unroll
    for (int i = 0; i < 4; i++) {
        ra[i] = *(const float4*)(Ag + (long)(32 * i) * 512 + 32);
        rb[i] = *(const float4*)(Bg + (long)(32 * i) * 512 + 32);
    }

    for (int ch = 0; ch < 16; ch++) {
        const uint32_t* as = A0 + (ch & 1) * 128 * PAD;
        const uint32_t* bs = B0 + (ch & 1) * 128 * PAD;
#pragma unroll
        for (int kt = 0; kt < 4; kt++) {
            const int k0 = kt * 8;
            uint32_t af[2][4];
#pragma unroll
            for (int mt = 0; mt < 2; mt++) {
                const int rr = mw * 32 + mt * 16 + r;
                af[mt][0] = as[rr * PAD + k0 + cq];
                af[mt][1] = as[(rr + 8) * PAD + k0 + cq];
                af[mt][2] = as[rr * PAD + k0 + cq + 4];
                af[mt][3] = as[(rr + 8) * PAD + k0 + cq + 4];
            }
            uint32_t bf[8][2];
#pragma unroll
            for (int t = 0; t < 8; t++) {
                const int nr = nw * 64 + t * 8 + r;
                bf[t][0] = bs[nr * PAD + k0 + cq];
                bf[t][1] = bs[nr * PAD + k0 + cq + 4];
            }
#pragma unroll
            for (int mt = 0; mt < 2; mt++)
#pragma unroll
                for (int t = 0; t < 8; t++)
                    mma_tf32(acc[mt][t], af[mt], bf[t][0], bf[t][1]);
        }
        if (ch < 15) {
            uint32_t* aw = A0 + ((ch + 1) & 1) * 128 * PAD;
            uint32_t* bw = B0 + ((ch + 1) & 1) * 128 * PAD;
#pragma unroll
            for (int i = 0; i < 4; i++) {
                uint4 ua = {tf32r(ra[i].x), tf32r(ra[i].y), tf32r(ra[i].z), tf32r(ra[i].w)};
                *(uint4*)&aw[(row_b + 32 * i) * PAD + c4 * 4] = ua;
                uint4 ub = {tf32r(rb[i].x), tf32r(rb[i].y), tf32r(rb[i].z), tf32r(rb[i].w)};
                *(uint4*)&bw[(row_b + 32 * i) * PAD + c4 * 4] = ub;
            }
            __syncthreads();
            if (ch < 14) {
                const int kn = (ch + 2) * 32;
#pragma unroll
                for (int i = 0; i < 4; i++) {
                    ra[i] = *(const float4*)(Ag + (long)(32 * i) * 512 + kn);
                    rb[i] = *(const float4*)(Bg + (long)(32 * i) * 512 + kn);
                }
            }
        }
    }

#pragma unroll
    for (int mt = 0; mt < 2; mt++) {
        const int row0 = m0 + mw * 32 + mt * 16 + r;
#pragma unroll
        for (int t = 0; t < 8; t++) {
            const int col = n0 + nw * 64 + t * 8 + 2 * cq;
            float2 b2 = {0.f, 0.f};
            if (HAS_BIAS) b2 = *(const float2*)(bias + col);
            float2 v0 = {acc[mt][t][0] + b2.x, acc[mt][t][1] + b2.y};
            *(float2*)(C + (long)row0 * N + col) = v0;
            float2 v1 = {acc[mt][t][2] + b2.x, acc[mt][t][3] + b2.y};
            *(float2*)(C + (long)(row0 + 8) * N + col) = v1;
        }
    }
}

// ---------------------------------------------------------------------------
// Flash attention, tf32 mma.sync — R7 config (known best): 64-query tile,
// 128 thr (4 warps x m16).  Changes vs R7: reversed q-tile schedule (heavy
// CTAs launch first) + __launch_bounds__(128,3) for guaranteed 3 CTAs/SM.
// Smem: Qb/Kb/Pb [64][68], Vb [64][72]  (70656 B).
// ---------------------------------------------------------------------------
__global__ void __launch_bounds__(128, 3)
flash_mma_kernel(const float* __restrict__ qkv, float* __restrict__ attn_out)
{
    extern __shared__ uint32_t fsm[];
    uint32_t* const Qb = fsm;                            // [64][68]
    uint32_t* const Kb = fsm + 64 * 68;                  // [64][68]
    uint32_t* const Pb = fsm + 2 * 64 * 68;              // [64][68]
    uint32_t* const Vb = fsm + 3 * 64 * 68;              // [64][72]

    const int tid = threadIdx.x, lane = tid & 31, w = tid >> 5;
    const int r = lane >> 2, cq = lane & 3;
    const int bh = blockIdx.y, b = bh >> 3, h = bh & 7;
    const int qi = gridDim.x - 1 - blockIdx.x;   // reversed: heavy CTAs first
    const int q0 = qi * 64;
    const float* base = qkv + (long)b * T * QKV_STRIDE + h * HK;

    const int c4 = tid & 15, rowq = tid >> 4;    // loader: 8 rows/iter

    // Load Q tile (tf32-rounded); visible after first loop-top sync.
#pragma unroll
    for (int i = 0; i < 8; i++) {
        const int row = rowq + 8 * i;
        float4 v = *(const float4*)(base + (long)(q0 + row) * QKV_STRIDE + c4 * 4);
        uint4 u = {tf32r(v.x), tf32r(v.y), tf32r(v.z), tf32r(v.w)};
        *(uint4*)&Qb[row * 68 + c4 * 4] = u;
    }

    float m0_ = -1e30f, m1_ = -1e30f, l0_ = 0.f, l1_ = 0.f;
    float oacc[8][4] = {};
    const int r0 = w * 16 + r;                   // warp rows r0, r0+8 (local)
    const int ntiles = qi + 1;

    for (int t0 = 0; t0 < ntiles; t0++) {
        const int j0 = t0 * 64;
        __syncthreads();   // prior readers of Kb/Vb done; Qb visible on t0=0
        {
            const float* kb = base + D;
            const float* vb = base + 2 * D;
#pragma unroll
            for (int i = 0; i < 8; i++) {
                const int row = rowq + 8 * i;
                float4 kv = *(const float4*)(kb + (long)(j0 + row) * QKV_STRIDE + c4 * 4);
                uint4 uk = {tf32r(kv.x), tf32r(kv.y), tf32r(kv.z), tf32r(kv.w)};
                *(uint4*)&Kb[row * 68 + c4 * 4] = uk;
                float4 vv = *(const float4*)(vb + (long)(j0 + row) * QKV_STRIDE + c4 * 4);
                uint4 uv = {tf32r(vv.x), tf32r(vv.y), tf32r(vv.z), tf32r(vv.w)};
                *(uint4*)&Vb[row * 72 + c4 * 4] = uv;
            }
        }
        __syncthreads();

        // S = Q @ K^T  (warp: 16x64)
        float s[8][4] = {};
#pragma unroll
        for (int kt = 0; kt < 8; kt++) {
            const int k0 = kt * 8;
            uint32_t a[4];
            a[0] = Qb[r0 * 68 + k0 + cq];
            a[1] = Qb[(r0 + 8) * 68 + k0 + cq];
            a[2] = Qb[r0 * 68 + k0 + cq + 4];
            a[3] = Qb[(r0 + 8) * 68 + k0 + cq + 4];
#pragma unroll
            for (int t = 0; t < 8; t++) {
                const uint32_t b0 = Kb[(t * 8 + r) * 68 + k0 + cq];
                const uint32_t b1 = Kb[(t * 8 + r) * 68 + k0 + cq + 4];
                mma_tf32(s[t], a, b0, b1);
            }
        }

        // scale + causal mask (diag tile only; local row/col valid there)
        const bool diag = (j0 == q0);
#pragma unroll
        for (int t = 0; t < 8; t++) {
            s[t][0] *= 0.125f; s[t][1] *= 0.125f;
            s[t][2] *= 0.125f; s[t][3] *= 0.125f;
            if (diag) {
                const int j = t * 8 + 2 * cq;
                if (j     > r0)     s[t][0] = -1e30f;
                if (j + 1 > r0)     s[t][1] = -1e30f;
                if (j     > r0 + 8) s[t][2] = -1e30f;
                if (j + 1 > r0 + 8) s[t][3] = -1e30f;
            }
        }

        // online softmax (rows r0, r0+8; 4 lanes share a row)
        float rm0 = -1e30f, rm1 = -1e30f;
#pragma unroll
        for (int t = 0; t < 8; t++) {
            rm0 = fmaxf(rm0, fmaxf(s[t][0], s[t][1]));
            rm1 = fmaxf(rm1, fmaxf(s[t][2], s[t][3]));
        }
        rm0 = fmaxf(rm0, __shfl_xor_sync(0xffffffffu, rm0, 1));
        rm0 = fmaxf(rm0, __shfl_xor_sync(0xffffffffu, rm0, 2));
        rm1 = fmaxf(rm1, __shfl_xor_sync(0xffffffffu, rm1, 1));
        rm1 = fmaxf(rm1, __shfl_xor_sync(0xffffffffu, rm1, 2));
        const float nm0 = fmaxf(m0_, rm0), nm1 = fmaxf(m1_, rm1);
        const float al0 = __expf(m0_ - nm0), al1 = __expf(m1_ - nm1);
        m0_ = nm0; m1_ = nm1;

        float rs0 = 0.f, rs1 = 0.f;
#pragma unroll
        for (int t = 0; t < 8; t++) {
            const float p0 = __expf(s[t][0] - nm0);
            const float p1 = __expf(s[t][1] - nm0);
            const float p2 = __expf(s[t][2] - nm1);
            const float p3 = __expf(s[t][3] - nm1);
            rs0 += p0 + p1; rs1 += p2 + p3;
            const int j = t * 8 + 2 * cq;
            Pb[r0 * 68 + j]           = tf32r(p0);
            Pb[r0 * 68 + j + 1]       = tf32r(p1);
            Pb[(r0 + 8) * 68 + j]     = tf32r(p2);
            Pb[(r0 + 8) * 68 + j + 1] = tf32r(p3);
        }
        rs0 += __shfl_xor_sync(0xffffffffu, rs0, 1);
        rs0 += __shfl_xor_sync(0xffffffffu, rs0, 2);
        rs1 += __shfl_xor_sync(0xffffffffu, rs1, 1);
        rs1 += __shfl_xor_sync(0xffffffffu, rs1, 2);
        l0_ = l0_ * al0 + rs0;
        l1_ = l1_ * al1 + rs1;
#pragma unroll
        for (int t = 0; t < 8; t++) {
            oacc[t][0] *= al0; oacc[t][1] *= al0;
            oacc[t][2] *= al1; oacc[t][3] *= al1;
        }
        __syncwarp();   // Pb rows are warp-private: cross-lane visibility only

        // O += P @ V
#pragma unroll
        for (int kt = 0; kt < 8; kt++) {
            const int k0 = kt * 8;
            uint32_t a[4];
            a[0] = Pb[r0 * 68 + k0 + cq];
            a[1] = Pb[(r0 + 8) * 68 + k0 + cq];
            a[2] = Pb[r0 * 68 + k0 + cq + 4];
            a[3] = Pb[(r0 + 8) * 68 + k0 + cq + 4];
#pragma unroll
            for (int t = 0; t < 8; t++) {
                const uint32_t b0 = Vb[(k0 + cq) * 72 + t * 8 + r];
                const uint32_t b1 = Vb[(k0 + cq + 4) * 72 + t * 8 + r];
                mma_tf32(oacc[t], a, b0, b1);
            }
        }
    }

    // Epilogue: normalize + write [B,T,H*K]
    const float inv0 = 1.f / l0_, inv1 = 1.f / l1_;
    float* ob = attn_out + ((long)b * T + q0) * D + h * HK;
#pragma unroll
    for (int t = 0; t < 8; t++) {
        const int col = t * 8 + 2 * cq;
        float2 v0 = {oacc[t][0] * inv0, oacc[t][1] * inv0};
        *(float2*)(ob + (long)r0 * D + col) = v0;
        float2 v1 = {oacc[t][2] * inv1, oacc[t][3] * inv1};
        *(float2*)(ob + (long)(r0 + 8) * D + col) = v1;
    }
}

// ---------------------------------------------------------------------------
extern "C" void kernel_launch(void* const* d_in, const int* in_sizes, int n_in,
                              void* d_out, int out_size)
{
    (void)out_size;
    const float *x = nullptr, *w_qkv = nullptr, *w_proj = nullptr, *b_proj = nullptr;
    for (int i = 0; i < n_in; i++) {
        switch (in_sizes[i]) {
            case MROWS * D: x      = (const float*)d_in[i]; break; // 4194304
            case 3 * D * D: w_qkv  = (const float*)d_in[i]; break; // 786432
            case D * D:     w_proj = (const float*)d_in[i]; break; // 262144
            case D:         b_proj = (const float*)d_in[i]; break; // 512
        }
    }
    float* out = (float*)d_out;

    float* qkv_buf = nullptr;
    float* attn_buf = nullptr;
    cudaGetSymbolAddress((void**)&qkv_buf, g_qkv);
    cudaGetSymbolAddress((void**)&attn_buf, g_attn);

    const int gemm_smem = 4 * 128 * 36 * 4;            // 73728
    const int attn_smem = (3 * 64 * 68 + 64 * 72) * 4; // 70656
    cudaFuncSetAttribute(gemm_mma_kernel<false>,
                         cudaFuncAttributeMaxDynamicSharedMemorySize, gemm_smem);
    cudaFuncSetAttribute(gemm_mma_kernel<true>,
                         cudaFuncAttributeMaxDynamicSharedMemorySize, gemm_smem);
    cudaFuncSetAttribute(flash_mma_kernel,
                         cudaFuncAttributeMaxDynamicSharedMemorySize, attn_smem);

    // 1) QKV projection: [8192,1536] = x @ w_qkv^T
    {
        dim3 grid(3 * D / 128, MROWS / 128);   // (12, 64)
        gemm_mma_kernel<false><<<grid, 256, gemm_smem>>>(x, w_qkv, nullptr,
                                                         qkv_buf, 3 * D);
    }
    // 2) Causal flash attention (tf32 mma, 64-query tiles, reversed sched)
    {
        dim3 grid(T / 64, Bb * Hh);            // (32, 32)
        flash_mma_kernel<<<grid, 128, attn_smem>>>(qkv_buf, attn_buf);
    }
    // 3) Output projection + bias
    {
        dim3 grid(D / 128, MROWS / 128);       // (4, 64)
        gemm_mma_kernel<true><<<grid, 256, gemm_smem>>>(attn_buf, w_proj, b_proj,
                                                        out, D);
    }
}

// round 17
// speedup vs baseline: 1.1141x; 1.0635x over previous
#include <cuda_runtime.h>
#include <cstdint>

// Problem constants
static constexpr int Bb = 4, T = 2048, D = 512, Hh = 8, HK = 64;
static constexpr int MROWS = Bb * T;          // 8192
static constexpr long QKV_STRIDE = 3 * D;     // 1536

// Scratch (device globals: allocation-free)
__device__ float g_qkv[MROWS * 3 * D];        // [8192, 1536]  (Q | K | V), tf32-rounded
__device__ float g_attn[MROWS * D];           // [8192, 512]   (B,T,H*K)

// ---------------------------------------------------------------------------
// Helpers (baseline PTX only — no 'a'-suffix ISA)
// ---------------------------------------------------------------------------
__device__ __forceinline__ uint32_t tf32r(float f) {
    uint32_t u;
    asm("cvt.rna.tf32.f32 %0, %1;" : "=r"(u) : "f"(f));
    return u;
}
__device__ __forceinline__ void mma_tf32(float* c, const uint32_t* a,
                                         uint32_t b0, uint32_t b1) {
    asm volatile(
        "mma.sync.aligned.m16n8k8.row.col.f32.tf32.tf32.f32 "
        "{%0,%1,%2,%3}, {%4,%5,%6,%7}, {%8,%9}, {%0,%1,%2,%3};"
        : "+f"(c[0]), "+f"(c[1]), "+f"(c[2]), "+f"(c[3])
        : "r"(a[0]), "r"(a[1]), "r"(a[2]), "r"(a[3]), "r"(b0), "r"(b1));
}
__device__ __forceinline__ uint32_t smem_u32(const void* p) {
    uint32_t a;
    asm("{ .reg .u64 t; cvta.to.shared.u64 t, %1; cvt.u32.u64 %0, t; }"
        : "=r"(a) : "l"(p));
    return a;
}
__device__ __forceinline__ void cp_async16(uint32_t saddr, const void* gptr) {
    asm volatile("cp.async.cg.shared.global [%0], [%1], 16;"
                 :: "r"(saddr), "l"(gptr) : "memory");
}
__device__ __forceinline__ void cp_commit() {
    asm volatile("cp.async.commit_group;" ::: "memory");
}
template<int N>
__device__ __forceinline__ void cp_wait() {
    asm volatile("cp.async.wait_group %0;" :: "n"(N) : "memory");
}

// ---------------------------------------------------------------------------
// tf32 mma.sync GEMM: C[M,N] = A[M,512] @ B[N,512]^T (+bias).
// 128x128 tile, 256 thr = 8 warps (4 m x 2 n), warp tile 32x64.
// BK=32, double-buffered smem (pad 36), register prefetch.
// RND_OUT: store C rna-rounded to tf32 (consumers feed it straight to mma).
// ---------------------------------------------------------------------------
template<bool HAS_BIAS, bool RND_OUT>
__global__ void __launch_bounds__(256, 2)
gemm_mma_kernel(const float* __restrict__ A, const float* __restrict__ Bw,
                const float* __restrict__ bias, float* __restrict__ C, int N)
{
    extern __shared__ uint32_t sm[];
    constexpr int PAD = 36;
    uint32_t* const A0 = sm;                // stage area: [2][128][36]
    uint32_t* const B0 = sm + 2 * 128 * PAD;

    const int tid = threadIdx.x, lane = tid & 31, w = tid >> 5;
    const int mw = w & 3, nw = w >> 2;
    const int m0 = blockIdx.y * 128, n0 = blockIdx.x * 128;
    const int r = lane >> 2, cq = lane & 3;

    const int c4 = tid & 7, row_b = tid >> 3;
    const float* Ag = A + (long)(m0 + row_b) * 512 + c4 * 4;
    const float* Bg = Bw + (long)(n0 + row_b) * 512 + c4 * 4;

    float acc[2][8][4] = {};
    float4 ra[4], rb[4];

#pragma unroll
    for (int i = 0; i < 4; i++) {
        ra[i] = *(const float4*)(Ag + (long)(32 * i) * 512);
        rb[i] = *(const float4*)(Bg + (long)(32 * i) * 512);
    }
#pragma unroll
    for (int i = 0; i < 4; i++) {
        uint4 ua = {tf32r(ra[i].x), tf32r(ra[i].y), tf32r(ra[i].z), tf32r(ra[i].w)};
        *(uint4*)&A0[(row_b + 32 * i) * PAD + c4 * 4] = ua;
        uint4 ub = {tf32r(rb[i].x), tf32r(rb[i].y), tf32r(rb[i].z), tf32r(rb[i].w)};
        *(uint4*)&B0[(row_b + 32 * i) * PAD + c4 * 4] = ub;
    }
    __syncthreads();
#pragma unroll
    for (int i = 0; i < 4; i++) {
        ra[i] = *(const float4*)(Ag + (long)(32 * i) * 512 + 32);
        rb[i] = *(const float4*)(Bg + (long)(32 * i) * 512 + 32);
    }

    for (int ch = 0; ch < 16; ch++) {
        const uint32_t* as = A0 + (ch & 1) * 128 * PAD;
        const uint32_t* bs = B0 + (ch & 1) * 128 * PAD;
#pragma unroll
        for (int kt = 0; kt < 4; kt++) {
            const int k0 = kt * 8;
            uint32_t af[2][4];
#pragma unroll
            for (int mt = 0; mt < 2; mt++) {
                const int rr = mw * 32 + mt * 16 + r;
                af[mt][0] = as[rr * PAD + k0 + cq];
                af[mt][1] = as[(rr + 8) * PAD + k0 + cq];
                af[mt][2] = as[rr * PAD + k0 + cq + 4];
                af[mt][3] = as[(rr + 8) * PAD + k0 + cq + 4];
            }
            uint32_t bf[8][2];
#pragma unroll
            for (int t = 0; t < 8; t++) {
                const int nr = nw * 64 + t * 8 + r;
                bf[t][0] = bs[nr * PAD + k0 + cq];
                bf[t][1] = bs[nr * PAD + k0 + cq + 4];
            }
#pragma unroll
            for (int mt = 0; mt < 2; mt++)
#pragma unroll
                for (int t = 0; t < 8; t++)
                    mma_tf32(acc[mt][t], af[mt], bf[t][0], bf[t][1]);
        }
        if (ch < 15) {
            uint32_t* aw = A0 + ((ch + 1) & 1) * 128 * PAD;
            uint32_t* bw = B0 + ((ch + 1) & 1) * 128 * PAD;
#pragma unroll
            for (int i = 0; i < 4; i++) {
                uint4 ua = {tf32r(ra[i].x), tf32r(ra[i].y), tf32r(ra[i].z), tf32r(ra[i].w)};
                *(uint4*)&aw[(row_b + 32 * i) * PAD + c4 * 4] = ua;
                uint4 ub = {tf32r(rb[i].x), tf32r(rb[i].y), tf32r(rb[i].z), tf32r(rb[i].w)};
                *(uint4*)&bw[(row_b + 32 * i) * PAD + c4 * 4] = ub;
            }
            __syncthreads();
            if (ch < 14) {
                const int kn = (ch + 2) * 32;
#pragma unroll
                for (int i = 0; i < 4; i++) {
                    ra[i] = *(const float4*)(Ag + (long)(32 * i) * 512 + kn);
                    rb[i] = *(const float4*)(Bg + (long)(32 * i) * 512 + kn);
                }
            }
        }
    }

#pragma unroll
    for (int mt = 0; mt < 2; mt++) {
        const int row0 = m0 + mw * 32 + mt * 16 + r;
#pragma unroll
        for (int t = 0; t < 8; t++) {
            const int col = n0 + nw * 64 + t * 8 + 2 * cq;
            float2 b2 = {0.f, 0.f};
            if (HAS_BIAS) b2 = *(const float2*)(bias + col);
            float2 v0 = {acc[mt][t][0] + b2.x, acc[mt][t][1] + b2.y};
            float2 v1 = {acc[mt][t][2] + b2.x, acc[mt][t][3] + b2.y};
            if (RND_OUT) {
                uint2 u0 = {tf32r(v0.x), tf32r(v0.y)};
                uint2 u1 = {tf32r(v1.x), tf32r(v1.y)};
                *(uint2*)(C + (long)row0 * N + col) = u0;
                *(uint2*)(C + (long)(row0 + 8) * N + col) = u1;
            } else {
                *(float2*)(C + (long)row0 * N + col) = v0;
                *(float2*)(C + (long)(row0 + 8) * N + col) = v1;
            }
        }
    }
}

// ---------------------------------------------------------------------------
// Flash attention, tf32 mma.sync. 64-query tile, 128 thr (4 warps x m16).
// qkv buffer is PRE-ROUNDED to tf32 by the QKV GEMM epilogue, so K/V stream
// in via raw cp.async (double-buffered, overlapped with compute) and Q is a
// raw copy — bit-identical numerics to the explicit-cvt version.
// Smem: Qb[64][68], Pb[64][68], Kb[2][64][68], Vb[2][64][72] = 106496 B.
// ---------------------------------------------------------------------------
__global__ void __launch_bounds__(128, 2)
flash_mma_kernel(const float* __restrict__ qkv, float* __restrict__ attn_out)
{
    extern __shared__ uint32_t fsm[];
    uint32_t* const Qb = fsm;                          // [64][68]
    uint32_t* const Pb = fsm + 64 * 68;                // [64][68]
    uint32_t* const Kb = fsm + 2 * 64 * 68;            // [2][64][68]
    uint32_t* const Vb = fsm + 4 * 64 * 68;            // [2][64][72]
    constexpr int KSTR = 64 * 68;                      // K buffer stride (words)
    constexpr int VSTR = 64 * 72;

    const int tid = threadIdx.x, lane = tid & 31, w = tid >> 5;
    const int r = lane >> 2, cq = lane & 3;
    const int bh = blockIdx.y, b = bh >> 3, h = bh & 7;
    const int qi = gridDim.x - 1 - blockIdx.x;   // heavy CTAs first
    const int q0 = qi * 64;
    const float* base = qkv + (long)b * T * QKV_STRIDE + h * HK;
    const float* kbg = base + D;
    const float* vbg = base + 2 * D;

    const int c4 = tid & 15, rowq = tid >> 4;    // loader: 8 rows/thread
    const uint32_t kb_s = smem_u32(Kb);
    const uint32_t vb_s = smem_u32(Vb);

    // Q tile: raw copy (values already tf32-rounded upstream).
#pragma unroll
    for (int i = 0; i < 8; i++) {
        const int row = rowq + 8 * i;
        float4 v = *(const float4*)(base + (long)(q0 + row) * QKV_STRIDE + c4 * 4);
        *(float4*)&Qb[row * 68 + c4 * 4] = v;
    }

    const int ntiles = qi + 1;

    // Prefetch tile 0 into buffer 0.
#pragma unroll
    for (int i = 0; i < 8; i++) {
        const int row = rowq + 8 * i;
        cp_async16(kb_s + (row * 68 + c4 * 4) * 4,
                   kbg + (long)row * QKV_STRIDE + c4 * 4);
        cp_async16(vb_s + (row * 72 + c4 * 4) * 4,
                   vbg + (long)row * QKV_STRIDE + c4 * 4);
    }
    cp_commit();

    float m0_ = -1e30f, m1_ = -1e30f, l0_ = 0.f, l1_ = 0.f;
    float oacc[8][4] = {};
    const int r0 = w * 16 + r;                   // warp rows r0, r0+8 (local)

    for (int t0 = 0; t0 < ntiles; t0++) {
        const int buf = t0 & 1;
        // Issue prefetch of tile t0+1 into the other buffer (safe: previous
        // iteration's trailing __syncthreads ordered all reads of it).
        if (t0 + 1 < ntiles) {
            const int jn = (t0 + 1) * 64;
            const uint32_t ko = (uint32_t)((buf ^ 1) * KSTR) * 4;
            const uint32_t vo = (uint32_t)((buf ^ 1) * VSTR) * 4;
#pragma unroll
            for (int i = 0; i < 8; i++) {
                const int row = rowq + 8 * i;
                cp_async16(kb_s + ko + (row * 68 + c4 * 4) * 4,
                           kbg + (long)(jn + row) * QKV_STRIDE + c4 * 4);
                cp_async16(vb_s + vo + (row * 72 + c4 * 4) * 4,
                           vbg + (long)(jn + row) * QKV_STRIDE + c4 * 4);
            }
            cp_commit();
            cp_wait<1>();      // tile t0's group complete (one pending)
        } else {
            cp_wait<0>();      // last tile: drain everything
        }
        __syncthreads();       // cross-thread visibility of Kb/Vb (+Qb on t0=0)

        const uint32_t* Kc = Kb + buf * KSTR;
        const uint32_t* Vc = Vb + buf * VSTR;

        // S = Q @ K^T  (warp: 16x64)
        float s[8][4] = {};
#pragma unroll
        for (int kt = 0; kt < 8; kt++) {
            const int k0 = kt * 8;
            uint32_t a[4];
            a[0] = Qb[r0 * 68 + k0 + cq];
            a[1] = Qb[(r0 + 8) * 68 + k0 + cq];
            a[2] = Qb[r0 * 68 + k0 + cq + 4];
            a[3] = Qb[(r0 + 8) * 68 + k0 + cq + 4];
#pragma unroll
            for (int t = 0; t < 8; t++) {
                const uint32_t b0 = Kc[(t * 8 + r) * 68 + k0 + cq];
                const uint32_t b1 = Kc[(t * 8 + r) * 68 + k0 + cq + 4];
                mma_tf32(s[t], a, b0, b1);
            }
        }

        // scale + causal mask (diag tile only; local coords valid there)
        const bool diag = (t0 * 64 == q0);
#pragma unroll
        for (int t = 0; t < 8; t++) {
            s[t][0] *= 0.125f; s[t][1] *= 0.125f;
            s[t][2] *= 0.125f; s[t][3] *= 0.125f;
            if (diag) {
                const int j = t * 8 + 2 * cq;
                if (j     > r0)     s[t][0] = -1e30f;
                if (j + 1 > r0)     s[t][1] = -1e30f;
                if (j     > r0 + 8) s[t][2] = -1e30f;
                if (j + 1 > r0 + 8) s[t][3] = -1e30f;
            }
        }

        // online softmax (rows r0, r0+8; 4 lanes share a row)
        float rm0 = -1e30f, rm1 = -1e30f;
#pragma unroll
        for (int t = 0; t < 8; t++) {
            rm0 = fmaxf(rm0, fmaxf(s[t][0], s[t][1]));
            rm1 = fmaxf(rm1, fmaxf(s[t][2], s[t][3]));
        }
        rm0 = fmaxf(rm0, __shfl_xor_sync(0xffffffffu, rm0, 1));
        rm0 = fmaxf(rm0, __shfl_xor_sync(0xffffffffu, rm0, 2));
        rm1 = fmaxf(rm1, __shfl_xor_sync(0xffffffffu, rm1, 1));
        rm1 = fmaxf(rm1, __shfl_xor_sync(0xffffffffu, rm1, 2));
        const float nm0 = fmaxf(m0_, rm0), nm1 = fmaxf(m1_, rm1);
        const float al0 = __expf(m0_ - nm0), al1 = __expf(m1_ - nm1);
        m0_ = nm0; m1_ = nm1;

        float rs0 = 0.f, rs1 = 0.f;
#pragma unroll
        for (int t = 0; t < 8; t++) {
            const float p0 = __expf(s[t][0] - nm0);
            const float p1 = __expf(s[t][1] - nm0);
            const float p2 = __expf(s[t][2] - nm1);
            const float p3 = __expf(s[t][3] - nm1);
            rs0 += p0 + p1; rs1 += p2 + p3;
            const int j = t * 8 + 2 * cq;
            Pb[r0 * 68 + j]           = tf32r(p0);
            Pb[r0 * 68 + j + 1]       = tf32r(p1);
            Pb[(r0 + 8) * 68 + j]     = tf32r(p2);
            Pb[(r0 + 8) * 68 + j + 1] = tf32r(p3);
        }
        rs0 += __shfl_xor_sync(0xffffffffu, rs0, 1);
        rs0 += __shfl_xor_sync(0xffffffffu, rs0, 2);
        rs1 += __shfl_xor_sync(0xffffffffu, rs1, 1);
        rs1 += __shfl_xor_sync(0xffffffffu, rs1, 2);
        l0_ = l0_ * al0 + rs0;
        l1_ = l1_ * al1 + rs1;
#pragma unroll
        for (int t = 0; t < 8; t++) {
            oacc[t][0] *= al0; oacc[t][1] *= al0;
            oacc[t][2] *= al1; oacc[t][3] *= al1;
        }
        __syncwarp();   // Pb rows are warp-private: cross-lane visibility only

        // O += P @ V
#pragma unroll
        for (int kt = 0; kt < 8; kt++) {
            const int k0 = kt * 8;
            uint32_t a[4];
            a[0] = Pb[r0 * 68 + k0 + cq];
            a[1] = Pb[(r0 + 8) * 68 + k0 + cq];
            a[2] = Pb[r0 * 68 + k0 + cq + 4];
            a[3] = Pb[(r0 + 8) * 68 + k0 + cq + 4];
#pragma unroll
            for (int t = 0; t < 8; t++) {
                const uint32_t b0 = Vc[(k0 + cq) * 72 + t * 8 + r];
                const uint32_t b1 = Vc[(k0 + cq + 4) * 72 + t * 8 + r];
                mma_tf32(oacc[t], a, b0, b1);
            }
        }
        __syncthreads();   // all reads of Kc/Vc done before t0+2 overwrites
    }

    // Epilogue: normalize + write [B,T,H*K]
    const float inv0 = 1.f / l0_, inv1 = 1.f / l1_;
    float* ob = attn_out + ((long)b * T + q0) * D + h * HK;
#pragma unroll
    for (int t = 0; t < 8; t++) {
        const int col = t * 8 + 2 * cq;
        float2 v0 = {oacc[t][0] * inv0, oacc[t][1] * inv0};
        *(float2*)(ob + (long)r0 * D + col) = v0;
        float2 v1 = {oacc[t][2] * inv1, oacc[t][3] * inv1};
        *(float2*)(ob + (long)(r0 + 8) * D + col) = v1;
    }
}

// ---------------------------------------------------------------------------
extern "C" void kernel_launch(void* const* d_in, const int* in_sizes, int n_in,
                              void* d_out, int out_size)
{
    (void)out_size;
    const float *x = nullptr, *w_qkv = nullptr, *w_proj = nullptr, *b_proj = nullptr;
    for (int i = 0; i < n_in; i++) {
        switch (in_sizes[i]) {
            case MROWS * D: x      = (const float*)d_in[i]; break; // 4194304
            case 3 * D * D: w_qkv  = (const float*)d_in[i]; break; // 786432
            case D * D:     w_proj = (const float*)d_in[i]; break; // 262144
            case D:         b_proj = (const float*)d_in[i]; break; // 512
        }
    }
    float* out = (float*)d_out;

    float* qkv_buf = nullptr;
    float* attn_buf = nullptr;
    cudaGetSymbolAddress((void**)&qkv_buf, g_qkv);
    cudaGetSymbolAddress((void**)&attn_buf, g_attn);

    const int gemm_smem = 4 * 128 * 36 * 4;                       // 73728
    const int attn_smem = (4 * 64 * 68 + 2 * 64 * 72) * 4;        // 106496
    cudaFuncSetAttribute(gemm_mma_kernel<false, true>,
                         cudaFuncAttributeMaxDynamicSharedMemorySize, gemm_smem);
    cudaFuncSetAttribute(gemm_mma_kernel<true, false>,
                         cudaFuncAttributeMaxDynamicSharedMemorySize, gemm_smem);
    cudaFuncSetAttribute(flash_mma_kernel,
                         cudaFuncAttributeMaxDynamicSharedMemorySize, attn_smem);

    // 1) QKV projection: [8192,1536] = x @ w_qkv^T  (output tf32-rounded)
    {
        dim3 grid(3 * D / 128, MROWS / 128);   // (12, 64)
        gemm_mma_kernel<false, true><<<grid, 256, gemm_smem>>>(x, w_qkv, nullptr,
                                                               qkv_buf, 3 * D);
    }
    // 2) Causal flash attention (tf32 mma, cp.async double-buffered K/V)
    {
        dim3 grid(T / 64, Bb * Hh);            // (32, 32)
        flash_mma_kernel<<<grid, 128, attn_smem>>>(qkv_buf, attn_buf);
    }
    // 3) Output projection + bias (exact fp32 epilogue)
    {
        dim3 grid(D / 128, MROWS / 128);       // (4, 64)
        gemm_mma_kernel<true, false><<<grid, 256, gemm_smem>>>(attn_buf, w_proj,
                                                               b_proj, out, D);
    }
}